// round 15
// baseline (speedup 1.0000x reference)
#include <cuda_runtime.h>

#define BB 2
#define NF 16
#define NG 4               // channel groups of 4 (float4)
#define HH 512
#define WW 512
#define H2 1024
#define W2 1024
#define CINc 50
#define HW (HH*WW)
#define HW2 (H2*W2)

// warp/combine tiles: 16x16 outputs at 512-res
#define TSW 16
#define TWW 34             // 2*TSW+2
#define TWNW (TWW*TWW)     // 1156
#define NPOS 5             // ceil(TWNW/256)

// conv tile (R11 geometry — proven best)
#define CTS 32
#define CTW 34
#define CTP 36
#define CNL 5

// -------- scratch (device globals; referenced ONLY from device code) --------
__device__ float4 g_tgt4 [(size_t)BB*NG*HW];   // tgt @512, channel-packed x4 (L2-resident)
__device__ float  g_warped[(size_t)BB*NF*HW];  // warped tgt @512, planar
__device__ float  g_adj  [(size_t)BB*2*HW];    // conv output, planar
__device__ float  g_newres[(size_t)BB*2*HW];   // combined residual, planar
__device__ float2 g_a1024[(size_t)BB*HW2];     // up(res)*2, interleaved
__device__ float2 g_b1024[(size_t)BB*HW2];     // up(adj)*2
__device__ float2 g_nr1024[(size_t)BB*HW2];    // up(new_res)*2

// -------- resize helpers (jax.image.resize bilinear; validated R1) --------
__device__ __forceinline__ void up_taps(int i, int n_in, int& t0, int& t1,
                                        float& w0, float& w1) {
    int k = i >> 1;
    if ((i & 1) == 0) { t0 = k - 1; t1 = k;     w0 = 0.25f; w1 = 0.75f; }
    else              { t0 = k;     t1 = k + 1; w0 = 0.75f; w1 = 0.25f; }
    if (t0 < 0)     { t0 = t1; w0 = 0.f; w1 = 1.f; }
    if (t1 >= n_in) { t1 = t0; w1 = 0.f; w0 = 1.f; }
}
__device__ __forceinline__ float dbase(int t) { return (t == 0 || t == 3) ? 0.25f : 0.75f; }

// composite 1D weights: warp-bilinear over the upsampled axis collapsed onto
// 3 source taps. i0 = floor(warped up-coord), fr = fraction. Masks = up-space bounds.
__device__ __forceinline__ void compose_dim(int i0, float fr, int& base, float w[3]) {
    bool m0 = (unsigned)i0 < (unsigned)H2;
    bool m1 = (unsigned)(i0 + 1) < (unsigned)H2;
    int c0 = min(max(i0, 0), H2 - 1);
    int c1 = min(max(i0 + 1, 0), H2 - 1);
    int t0a, t1a, t0b, t1b; float a0, a1, b0, b1;
    up_taps(c0, HH, t0a, t1a, a0, a1);
    up_taps(c1, HH, t0b, t1b, b0, b1);
    float f0 = m0 ? (1.f - fr) : 0.f;
    float f1 = m1 ? fr : 0.f;
    int bs = min(min(t0a, t1a), min(t0b, t1b));
    if (bs > HH - 3) bs = HH - 3;
    #pragma unroll
    for (int j = 0; j < 3; j++) {
        float wv = 0.f;
        wv += (t0a - bs == j) ? f0 * a0 : 0.f;
        wv += (t1a - bs == j) ? f0 * a1 : 0.f;
        wv += (t0b - bs == j) ? f1 * b0 : 0.f;
        wv += (t1b - bs == j) ? f1 * b1 : 0.f;
        w[j] = wv;
    }
    base = bs;
}

// -------- kernel 1: pack tgt channels (x4) + vectorized src pass-through -------
__global__ void __launch_bounds__(256) k_pack(const float* __restrict__ x,
                                              float* __restrict__ out) {
    int idx = blockIdx.x * blockDim.x + threadIdx.x;
    if (idx >= BB * (HW / 4)) return;
    int p4 = idx & (HW / 4 - 1), b = idx >> 16;
    int pix = 4 * p4;
    const float* xb = x + (size_t)b * 2 * NF * HW + pix;
    // pass-through: out[b][0..15] = x[b][0..15], float4 over pixels
    float* ob = out + (size_t)b * 2 * NF * HW + pix;
    #pragma unroll
    for (int c = 0; c < NF; c++)
        *(float4*)(ob + (size_t)c * HW) = *(const float4*)(xb + (size_t)c * HW);
    // pack tgt channels 16..31 into float4 channel groups
    const float* tb = xb + (size_t)NF * HW;
    float4* pb = g_tgt4 + (size_t)b * NG * HW + pix;
    #pragma unroll
    for (int g = 0; g < NG; g++) {
        float4 r0 = *(const float4*)(tb + (size_t)(4 * g + 0) * HW);
        float4 r1 = *(const float4*)(tb + (size_t)(4 * g + 1) * HW);
        float4 r2 = *(const float4*)(tb + (size_t)(4 * g + 2) * HW);
        float4 r3 = *(const float4*)(tb + (size_t)(4 * g + 3) * HW);
        float4* o = pb + (size_t)g * HW;
        o[0] = make_float4(r0.x, r1.x, r2.x, r3.x);
        o[1] = make_float4(r0.y, r1.y, r2.y, r3.y);
        o[2] = make_float4(r0.z, r1.z, r2.z, r3.z);
        o[3] = make_float4(r0.w, r1.w, r2.w, r3.w);
    }
}

// -------- kernel 2: upsample a 2ch 512 field ->1024, *2, interleaved float2 ----
__global__ void __launch_bounds__(256) k_up_res(const float* __restrict__ ext,
                                                int src_sel, int dst_sel) {
    int idx = blockIdx.x * blockDim.x + threadIdx.x;
    if (idx >= BB * H2 * (W2 / 4)) return;
    int xq = idx & (W2 / 4 - 1);
    int yy = (idx >> 8) & (H2 - 1);
    int b  = idx >> 18;
    int m = 2 * xq;
    int mm1 = max(m - 1, 0), mp2 = min(m + 2, WW - 1);
    float a00 = (m == 0) ? 0.f : 0.25f,  a01 = (m == 0) ? 1.f : 0.75f;
    float a30 = (m == WW - 2) ? 1.f : 0.75f, a31 = (m == WW - 2) ? 0.f : 0.25f;
    int ty0, ty1; float wy0, wy1;
    up_taps(yy, HH, ty0, ty1, wy0, wy1);
    int r0 = ty0 * WW, r1 = ty1 * WW;

    const float* src = (src_sel == 0) ? ext : ((src_sel == 1) ? g_adj : g_newres);
    const float* p0 = src + (size_t)b * 2 * HW;
    const float* p1 = p0 + HW;
    float ox[4], oy[4];
    {
        float s0 = p0[r0 + mm1]   * wy0 + p0[r1 + mm1]   * wy1;
        float s1 = p0[r0 + m]     * wy0 + p0[r1 + m]     * wy1;
        float s2 = p0[r0 + m + 1] * wy0 + p0[r1 + m + 1] * wy1;
        float s3 = p0[r0 + mp2]   * wy0 + p0[r1 + mp2]   * wy1;
        ox[0] = a00 * s0 + a01 * s1;  ox[1] = 0.75f * s1 + 0.25f * s2;
        ox[2] = 0.25f * s1 + 0.75f * s2;  ox[3] = a30 * s2 + a31 * s3;
    }
    {
        float s0 = p1[r0 + mm1]   * wy0 + p1[r1 + mm1]   * wy1;
        float s1 = p1[r0 + m]     * wy0 + p1[r1 + m]     * wy1;
        float s2 = p1[r0 + m + 1] * wy0 + p1[r1 + m + 1] * wy1;
        float s3 = p1[r0 + mp2]   * wy0 + p1[r1 + mp2]   * wy1;
        oy[0] = a00 * s0 + a01 * s1;  oy[1] = 0.75f * s1 + 0.25f * s2;
        oy[2] = 0.25f * s1 + 0.75f * s2;  oy[3] = a30 * s2 + a31 * s3;
    }
    float2* dst = (dst_sel == 0) ? g_a1024 : ((dst_sel == 1) ? g_b1024 : g_nr1024);
    float4* ob = (float4*)(dst + (size_t)b * HW2 + (size_t)yy * W2 + 4 * xq);
    ob[0] = make_float4(2.f * ox[0], 2.f * oy[0], 2.f * ox[1], 2.f * oy[1]);
    ob[1] = make_float4(2.f * ox[2], 2.f * oy[2], 2.f * ox[3], 2.f * oy[3]);
}

// -------- fused: composite 9-tap gather from 512 src -> warp+downsample --------
__global__ void __launch_bounds__(256) k_warpdown(
        float* __restrict__ out, int field_sel, int to_final) {
    __shared__ float4 s_w[TWNW];
    int b = blockIdx.z;
    int x0 = blockIdx.x * TSW, y0 = blockIdx.y * TSW;
    int gx0 = 2 * x0 - 1, gy0 = 2 * y0 - 1;
    int tid = threadIdx.x;

    const float2* fld = ((field_sel == 0) ? g_a1024 : g_nr1024) + (size_t)b * HW2;

    int   rbase[NPOS];
    float rwx[NPOS][3], rwy[NPOS][3];
    #pragma unroll
    for (int k = 0; k < NPOS; k++) {
        int i = tid + 256 * k;
        if (i < TWNW) {
            int r = i / TWW, cc = i - r * TWW;
            int Y = min(max(gy0 + r, 0), H2 - 1);
            int X = min(max(gx0 + cc, 0), W2 - 1);
            float2 f = fld[Y * W2 + X];
            float sx = (float)(gx0 + cc) + f.x;
            float sy = (float)(gy0 + r) + f.y;
            float xf = floorf(sx), yf = floorf(sy);
            float fx = sx - xf, fy = sy - yf;
            int ix0 = (int)xf, iy0 = (int)yf;
            int bxv, byv;
            compose_dim(ix0, fx, bxv, rwx[k]);
            compose_dim(iy0, fy, byv, rwy[k]);
            rbase[k] = byv * WW + bxv;
        }
    }

    const float4* src = g_tgt4 + (size_t)b * NG * HW;
    float* dstb = to_final ? (out + ((size_t)b * 2 * NF + NF) * HW)
                           : (g_warped + (size_t)b * NF * HW);
    int lx = tid & (TSW - 1), ly = tid >> 4;
    int yy = y0 + ly, xx = x0 + lx;
    float invsy = (yy == 0 || yy == HH - 1) ? (1.f / 1.75f) : 0.5f;
    float invsx = (xx == 0 || xx == WW - 1) ? (1.f / 1.75f) : 0.5f;
    float wyv[4], wxv[4];
    #pragma unroll
    for (int t = 0; t < 4; t++) {
        wyv[t] = ((unsigned)(gy0 + 2 * ly + t) < H2) ? dbase(t) * invsy : 0.f;
        wxv[t] = ((unsigned)(gx0 + 2 * lx + t) < W2) ? dbase(t) * invsx : 0.f;
    }
    int sbase = (2 * ly) * TWW + 2 * lx;
    int opix = yy * WW + xx;

    for (int g = 0; g < NG; g++) {
        const float4* p = src + (size_t)g * HW;
        #pragma unroll
        for (int k = 0; k < NPOS; k++) {
            int i = tid + 256 * k;
            if (i < TWNW) {
                const float4* q = p + rbase[k];
                float wx0 = rwx[k][0], wx1 = rwx[k][1], wx2 = rwx[k][2];
                float4 acc = make_float4(0.f, 0.f, 0.f, 0.f);
                #pragma unroll
                for (int j = 0; j < 3; j++) {
                    float4 v0 = q[j * WW], v1 = q[j * WW + 1], v2 = q[j * WW + 2];
                    float wy = rwy[k][j];
                    acc.x += wy * (wx0 * v0.x + wx1 * v1.x + wx2 * v2.x);
                    acc.y += wy * (wx0 * v0.y + wx1 * v1.y + wx2 * v2.y);
                    acc.z += wy * (wx0 * v0.z + wx1 * v1.z + wx2 * v2.z);
                    acc.w += wy * (wx0 * v0.w + wx1 * v1.w + wx2 * v2.w);
                }
                s_w[i] = acc;
            }
        }
        __syncthreads();
        float4 acc = make_float4(0.f, 0.f, 0.f, 0.f);
        #pragma unroll
        for (int ty = 0; ty < 4; ty++) {
            const float4* sr = s_w + sbase + ty * TWW;
            float4 rowv = make_float4(0.f, 0.f, 0.f, 0.f);
            #pragma unroll
            for (int tx = 0; tx < 4; tx++) {
                float4 v = sr[tx];
                float w = wxv[tx];
                rowv.x += w * v.x; rowv.y += w * v.y;
                rowv.z += w * v.z; rowv.w += w * v.w;
            }
            float w = wyv[ty];
            acc.x += w * rowv.x; acc.y += w * rowv.y;
            acc.z += w * rowv.z; acc.w += w * rowv.w;
        }
        dstb[(size_t)(4 * g + 0) * HW + opix] = acc.x;
        dstb[(size_t)(4 * g + 1) * HW + opix] = acc.y;
        dstb[(size_t)(4 * g + 2) * HW + opix] = acc.z;
        dstb[(size_t)(4 * g + 3) * HW + opix] = acc.w;
        __syncthreads();
    }
}

// -------- 3x3 conv 50->2: smem-tiled 32x32, register double-buffer (R11) ------
__global__ void __launch_bounds__(256) k_conv(
        const float* __restrict__ x, const float* __restrict__ res,
        const float* __restrict__ Wc, const float* __restrict__ bias) {
    __shared__ float sw[2 * CINc * 9];
    __shared__ float tile[2][CTW * CTP];
    int tid = threadIdx.x;
    for (int i = tid; i < 2 * CINc * 9; i += 256) sw[i] = Wc[i];

    int b = blockIdx.z;
    int x0 = blockIdx.x * CTS, y0 = blockIdx.y * CTS;
    int lx = tid & 31, ly4 = tid >> 5;

    const float* xb = x + (size_t)b * 2 * NF * HW;
    const float* wb = g_warped + (size_t)b * NF * HW;
    const float* rb = res + (size_t)b * 2 * HW;

    int  sofs[CNL], gofs[CNL];
    bool inb[CNL];
    #pragma unroll
    for (int k = 0; k < CNL; k++) {
        int i = tid + 256 * k;
        bool valid = (i < CTW * CTW);
        int r = i / CTW, col = i - r * CTW;
        int gy = y0 - 1 + r, gx = x0 - 1 + col;
        inb[k]  = valid && ((unsigned)gy < HH) && ((unsigned)gx < WW);
        sofs[k] = valid ? (r * CTP + col) : 0;
        gofs[k] = inb[k] ? (gy * WW + gx) : 0;
        if (!valid) sofs[k] = -1;
    }

    float a0[4] = {0.f, 0.f, 0.f, 0.f};
    float a1[4] = {0.f, 0.f, 0.f, 0.f};

    float ld[CNL];
    #pragma unroll
    for (int k = 0; k < CNL; k++) ld[k] = inb[k] ? xb[gofs[k]] : 0.f;
    #pragma unroll
    for (int k = 0; k < CNL; k++) if (sofs[k] >= 0) tile[0][sofs[k]] = ld[k];
    __syncthreads();

    int base = (ly4 * 4) * CTP + lx;

    #pragma unroll 1
    for (int c = 0; c < CINc; c++) {
        if (c + 1 < CINc) {
            int cn = c + 1;
            const float* p = (cn < 32) ? (xb + (size_t)cn * HW)
                           : (cn < 48) ? (wb + (size_t)(cn - 32) * HW)
                                       : (rb + (size_t)(cn - 48) * HW);
            #pragma unroll
            for (int k = 0; k < CNL; k++) ld[k] = inb[k] ? p[gofs[k]] : 0.f;
        }

        const float* tl = tile[c & 1];
        const float* q = sw + c * 9;
        const float* u = sw + CINc * 9 + c * 9;
        float q0 = q[0], q1 = q[1], q2 = q[2], q3 = q[3], q4 = q[4];
        float q5 = q[5], q6 = q[6], q7 = q[7], q8 = q[8];
        float u0 = u[0], u1 = u[1], u2 = u[2], u3 = u[3], u4 = u[4];
        float u5 = u[5], u6 = u[6], u7 = u[7], u8 = u[8];
        float v[6][3];
        #pragma unroll
        for (int r6 = 0; r6 < 6; r6++) {
            v[r6][0] = tl[base + r6 * CTP];
            v[r6][1] = tl[base + r6 * CTP + 1];
            v[r6][2] = tl[base + r6 * CTP + 2];
        }
        #pragma unroll
        for (int k = 0; k < 4; k++) {
            a0[k] += v[k][0] * q0 + v[k][1] * q1 + v[k][2] * q2
                   + v[k+1][0] * q3 + v[k+1][1] * q4 + v[k+1][2] * q5
                   + v[k+2][0] * q6 + v[k+2][1] * q7 + v[k+2][2] * q8;
            a1[k] += v[k][0] * u0 + v[k][1] * u1 + v[k][2] * u2
                   + v[k+1][0] * u3 + v[k+1][1] * u4 + v[k+1][2] * u5
                   + v[k+2][0] * u6 + v[k+2][1] * u7 + v[k+2][2] * u8;
        }

        if (c + 1 < CINc) {
            float* tn = tile[(c + 1) & 1];
            #pragma unroll
            for (int k = 0; k < CNL; k++) if (sofs[k] >= 0) tn[sofs[k]] = ld[k];
        }
        __syncthreads();
    }

    float b0 = bias[0], b1 = bias[1];
    float* o = g_adj + (size_t)b * 2 * HW;
    #pragma unroll
    for (int k = 0; k < 4; k++) {
        int pc = (y0 + ly4 * 4 + k) * WW + x0 + lx;
        o[pc]      = a0[k] + b0;
        o[HW + pc] = a1[k] + b1;
    }
}

// -------- fused: warp a1024 by b1024 (tables) -> downsample*0.5 + adj ----------
__global__ void __launch_bounds__(256) k_combine() {
    __shared__ float2 s_w[TWNW];
    int b = blockIdx.z;
    int x0 = blockIdx.x * TSW, y0 = blockIdx.y * TSW;
    int gx0 = 2 * x0 - 1, gy0 = 2 * y0 - 1;
    int tid = threadIdx.x;

    const float2* bf = g_b1024 + (size_t)b * HW2;
    const float2* af = g_a1024 + (size_t)b * HW2;

    #pragma unroll
    for (int k = 0; k < NPOS; k++) {
        int i = tid + 256 * k;
        if (i < TWNW) {
            int r = i / TWW, cc = i - r * TWW;
            int Y = min(max(gy0 + r, 0), H2 - 1);
            int X = min(max(gx0 + cc, 0), W2 - 1);
            float2 f = bf[Y * W2 + X];
            float sx = (float)(gx0 + cc) + f.x;
            float sy = (float)(gy0 + r) + f.y;
            float xf = floorf(sx), yf = floorf(sy);
            float fx = sx - xf, fy = sy - yf;
            int ix0 = (int)xf, iy0 = (int)yf;
            bool bx0 = (unsigned)ix0 < W2, bx1 = (unsigned)(ix0 + 1) < W2;
            bool by0 = (unsigned)iy0 < H2, by1 = (unsigned)(iy0 + 1) < H2;
            float wx0 = bx0 ? (1.f - fx) : 0.f, wx1 = bx1 ? fx : 0.f;
            float wy0 = by0 ? (1.f - fy) : 0.f, wy1 = by1 ? fy : 0.f;
            float w00 = wy0 * wx0, w01 = wy0 * wx1, w10 = wy1 * wx0, w11 = wy1 * wx1;
            int cx0 = min(max(ix0, 0), W2 - 1), cx1 = min(max(ix0 + 1, 0), W2 - 1);
            int cy0 = min(max(iy0, 0), H2 - 1), cy1 = min(max(iy0 + 1, 0), H2 - 1);
            int o00 = cy0 * W2 + cx0;
            int dxo = cx1 - cx0;
            int o10 = o00 + (cy1 - cy0) * W2;
            float2 v00 = af[o00], v01 = af[o00 + dxo];
            float2 v10 = af[o10], v11 = af[o10 + dxo];
            s_w[i] = make_float2(
                w00 * v00.x + w01 * v01.x + w10 * v10.x + w11 * v11.x,
                w00 * v00.y + w01 * v01.y + w10 * v10.y + w11 * v11.y);
        }
    }
    __syncthreads();

    int lx = tid & (TSW - 1), ly = tid >> 4;
    int yy = y0 + ly, xx = x0 + lx;
    float invsy = (yy == 0 || yy == HH - 1) ? (1.f / 1.75f) : 0.5f;
    float invsx = (xx == 0 || xx == WW - 1) ? (1.f / 1.75f) : 0.5f;
    float wyv[4], wxv[4];
    #pragma unroll
    for (int t = 0; t < 4; t++) {
        wyv[t] = ((unsigned)(gy0 + 2 * ly + t) < H2) ? dbase(t) * invsy : 0.f;
        wxv[t] = ((unsigned)(gx0 + 2 * lx + t) < W2) ? dbase(t) * invsx : 0.f;
    }
    int sbase = (2 * ly) * TWW + 2 * lx;
    float accx = 0.f, accy = 0.f;
    #pragma unroll
    for (int ty = 0; ty < 4; ty++) {
        const float2* sr = s_w + sbase + ty * TWW;
        float rx = wxv[0] * sr[0].x + wxv[1] * sr[1].x + wxv[2] * sr[2].x + wxv[3] * sr[3].x;
        float ry = wxv[0] * sr[0].y + wxv[1] * sr[1].y + wxv[2] * sr[2].y + wxv[3] * sr[3].y;
        accx += wyv[ty] * rx;
        accy += wyv[ty] * ry;
    }
    int p = yy * WW + xx;
    const float* ad = g_adj + (size_t)b * 2 * HW;
    float* nr = g_newres + (size_t)b * 2 * HW;
    nr[p]      = ad[p]      + 0.5f * accx;
    nr[HW + p] = ad[HW + p] + 0.5f * accy;
}

// -------- launch --------
extern "C" void kernel_launch(void* const* d_in, const int* in_sizes, int n_in,
                              void* d_out, int out_size) {
    const float* x    = (const float*)d_in[0];
    const float* res  = (const float*)d_in[1];
    const float* Wc   = (const float*)d_in[2];
    const float* bias = (const float*)d_in[3];
    float* out = (float*)d_out;

    const int T = 256;
    dim3 gp((BB * (HW / 4) + T - 1) / T);
    dim3 gu((BB * H2 * (W2 / 4) + T - 1) / T);
    dim3 gcv(WW / CTS, HH / CTS, BB);
    dim3 gw(HH / TSW, WW / TSW, BB);

    k_pack<<<gp, T>>>(x, out);                    // tgt -> g_tgt4 + src pass-through
    k_up_res<<<gu, T>>>(res, 0, 0);               // res -> g_a1024 (*2)
    k_warpdown<<<gw, T>>>(nullptr, 0, 0);         // 9-tap warp by a1024 -> g_warped
    k_conv<<<gcv, T>>>(x, res, Wc, bias);         // -> g_adj
    k_up_res<<<gu, T>>>(nullptr, 1, 1);           // adj -> g_b1024 (*2)
    k_combine<<<gw, T>>>();                       // -> g_newres
    k_up_res<<<gu, T>>>(nullptr, 2, 2);           // new_res -> g_nr1024 (*2)
    k_warpdown<<<gw, T>>>(out, 1, 1);             // 9-tap warp by nr1024 -> out[16..31]
}

// round 16
// speedup vs baseline: 1.0513x; 1.0513x over previous
#include <cuda_runtime.h>

#define BB 2
#define NF 16
#define NG 4               // channel groups of 4 (float4)
#define HH 512
#define WW 512
#define H2 1024
#define W2 1024
#define CINc 50
#define HW (HH*WW)
#define HW2 (H2*W2)

// warp/combine tiles: 16x16 outputs at 512-res
#define TSW 16
#define TWW 34             // 2*TSW+2
#define TWNW (TWW*TWW)     // 1156
#define NPOS 5             // ceil(TWNW/256)

// conv tile (R11 geometry — proven best)
#define CTS 32
#define CTW 34
#define CTP 36
#define CNL 5

// -------- scratch (device globals; referenced ONLY from device code) --------
__device__ float4 g_tgt4 [(size_t)BB*NG*HW];   // tgt @512, channel-packed x4 (L2-resident)
__device__ float  g_warped[(size_t)BB*NF*HW];  // warped tgt @512, planar
__device__ float  g_adj  [(size_t)BB*2*HW];    // conv output, planar
__device__ float  g_newres[(size_t)BB*2*HW];   // combined residual, planar
__device__ float2 g_a1024[(size_t)BB*HW2];     // up(res)*2, interleaved
__device__ float2 g_b1024[(size_t)BB*HW2];     // up(adj)*2
__device__ float2 g_nr1024[(size_t)BB*HW2];    // up(new_res)*2

// -------- resize helpers (jax.image.resize bilinear; validated R1) --------
__device__ __forceinline__ void up_taps(int i, int n_in, int& t0, int& t1,
                                        float& w0, float& w1) {
    int k = i >> 1;
    if ((i & 1) == 0) { t0 = k - 1; t1 = k;     w0 = 0.25f; w1 = 0.75f; }
    else              { t0 = k;     t1 = k + 1; w0 = 0.75f; w1 = 0.25f; }
    if (t0 < 0)     { t0 = t1; w0 = 0.f; w1 = 1.f; }
    if (t1 >= n_in) { t1 = t0; w1 = 0.f; w0 = 1.f; }
}
__device__ __forceinline__ float dbase(int t) { return (t == 0 || t == 3) ? 0.25f : 0.75f; }

// composite 1D weights: warp-bilinear over the upsampled axis collapsed onto
// 3 source taps (validated R14).
__device__ __forceinline__ void compose_dim(int i0, float fr, int& base, float w[3]) {
    bool m0 = (unsigned)i0 < (unsigned)H2;
    bool m1 = (unsigned)(i0 + 1) < (unsigned)H2;
    int c0 = min(max(i0, 0), H2 - 1);
    int c1 = min(max(i0 + 1, 0), H2 - 1);
    int t0a, t1a, t0b, t1b; float a0, a1, b0, b1;
    up_taps(c0, HH, t0a, t1a, a0, a1);
    up_taps(c1, HH, t0b, t1b, b0, b1);
    float f0 = m0 ? (1.f - fr) : 0.f;
    float f1 = m1 ? fr : 0.f;
    int bs = min(min(t0a, t1a), min(t0b, t1b));
    if (bs > HH - 3) bs = HH - 3;
    #pragma unroll
    for (int j = 0; j < 3; j++) {
        float wv = 0.f;
        wv += (t0a - bs == j) ? f0 * a0 : 0.f;
        wv += (t1a - bs == j) ? f0 * a1 : 0.f;
        wv += (t0b - bs == j) ? f1 * b0 : 0.f;
        wv += (t1b - bs == j) ? f1 * b1 : 0.f;
        w[j] = wv;
    }
    base = bs;
}

// -------- kernel 1: pack tgt channels into float4 groups @512 (R14 form) ------
__global__ void __launch_bounds__(256) k_pack(const float* __restrict__ x) {
    int idx = blockIdx.x * blockDim.x + threadIdx.x;
    if (idx >= BB * HW) return;
    int pix = idx & (HW - 1), b = idx >> 18;
    const float* xb = x + ((size_t)b * 2 * NF + NF) * HW + pix;
    float4* ob = g_tgt4 + (size_t)b * NG * HW + pix;
    #pragma unroll
    for (int g = 0; g < NG; g++) {
        float4 o;
        o.x = xb[(size_t)(4 * g + 0) * HW];
        o.y = xb[(size_t)(4 * g + 1) * HW];
        o.z = xb[(size_t)(4 * g + 2) * HW];
        o.w = xb[(size_t)(4 * g + 3) * HW];
        ob[(size_t)g * HW] = o;
    }
}

// -------- kernel 2: upsample a 2ch 512 field ->1024, *2, interleaved float2 ----
__global__ void __launch_bounds__(256) k_up_res(const float* __restrict__ ext,
                                                int src_sel, int dst_sel) {
    int idx = blockIdx.x * blockDim.x + threadIdx.x;
    if (idx >= BB * H2 * (W2 / 4)) return;
    int xq = idx & (W2 / 4 - 1);
    int yy = (idx >> 8) & (H2 - 1);
    int b  = idx >> 18;
    int m = 2 * xq;
    int mm1 = max(m - 1, 0), mp2 = min(m + 2, WW - 1);
    float a00 = (m == 0) ? 0.f : 0.25f,  a01 = (m == 0) ? 1.f : 0.75f;
    float a30 = (m == WW - 2) ? 1.f : 0.75f, a31 = (m == WW - 2) ? 0.f : 0.25f;
    int ty0, ty1; float wy0, wy1;
    up_taps(yy, HH, ty0, ty1, wy0, wy1);
    int r0 = ty0 * WW, r1 = ty1 * WW;

    const float* src = (src_sel == 0) ? ext : ((src_sel == 1) ? g_adj : g_newres);
    const float* p0 = src + (size_t)b * 2 * HW;
    const float* p1 = p0 + HW;
    float ox[4], oy[4];
    {
        float s0 = p0[r0 + mm1]   * wy0 + p0[r1 + mm1]   * wy1;
        float s1 = p0[r0 + m]     * wy0 + p0[r1 + m]     * wy1;
        float s2 = p0[r0 + m + 1] * wy0 + p0[r1 + m + 1] * wy1;
        float s3 = p0[r0 + mp2]   * wy0 + p0[r1 + mp2]   * wy1;
        ox[0] = a00 * s0 + a01 * s1;  ox[1] = 0.75f * s1 + 0.25f * s2;
        ox[2] = 0.25f * s1 + 0.75f * s2;  ox[3] = a30 * s2 + a31 * s3;
    }
    {
        float s0 = p1[r0 + mm1]   * wy0 + p1[r1 + mm1]   * wy1;
        float s1 = p1[r0 + m]     * wy0 + p1[r1 + m]     * wy1;
        float s2 = p1[r0 + m + 1] * wy0 + p1[r1 + m + 1] * wy1;
        float s3 = p1[r0 + mp2]   * wy0 + p1[r1 + mp2]   * wy1;
        oy[0] = a00 * s0 + a01 * s1;  oy[1] = 0.75f * s1 + 0.25f * s2;
        oy[2] = 0.25f * s1 + 0.75f * s2;  oy[3] = a30 * s2 + a31 * s3;
    }
    float2* dst = (dst_sel == 0) ? g_a1024 : ((dst_sel == 1) ? g_b1024 : g_nr1024);
    float4* ob = (float4*)(dst + (size_t)b * HW2 + (size_t)yy * W2 + 4 * xq);
    ob[0] = make_float4(2.f * ox[0], 2.f * oy[0], 2.f * ox[1], 2.f * oy[1]);
    ob[1] = make_float4(2.f * ox[2], 2.f * oy[2], 2.f * ox[3], 2.f * oy[3]);
}

// -------- fused: composite 9-tap gather from 512 src -> warp+downsample --------
__global__ void __launch_bounds__(256) k_warpdown(
        float* __restrict__ out, int field_sel, int to_final) {
    __shared__ float4 s_w[TWNW];
    int b = blockIdx.z;
    int x0 = blockIdx.x * TSW, y0 = blockIdx.y * TSW;
    int gx0 = 2 * x0 - 1, gy0 = 2 * y0 - 1;
    int tid = threadIdx.x;

    const float2* fld = ((field_sel == 0) ? g_a1024 : g_nr1024) + (size_t)b * HW2;

    int   rbase[NPOS];
    float rwx[NPOS][3], rwy[NPOS][3];
    #pragma unroll
    for (int k = 0; k < NPOS; k++) {
        int i = tid + 256 * k;
        if (i < TWNW) {
            int r = i / TWW, cc = i - r * TWW;
            int Y = min(max(gy0 + r, 0), H2 - 1);
            int X = min(max(gx0 + cc, 0), W2 - 1);
            float2 f = fld[Y * W2 + X];
            float sx = (float)(gx0 + cc) + f.x;
            float sy = (float)(gy0 + r) + f.y;
            float xf = floorf(sx), yf = floorf(sy);
            float fx = sx - xf, fy = sy - yf;
            int ix0 = (int)xf, iy0 = (int)yf;
            int bxv, byv;
            compose_dim(ix0, fx, bxv, rwx[k]);
            compose_dim(iy0, fy, byv, rwy[k]);
            rbase[k] = byv * WW + bxv;
        }
    }

    const float4* src = g_tgt4 + (size_t)b * NG * HW;
    float* dstb = to_final ? (out + ((size_t)b * 2 * NF + NF) * HW)
                           : (g_warped + (size_t)b * NF * HW);
    int lx = tid & (TSW - 1), ly = tid >> 4;
    int yy = y0 + ly, xx = x0 + lx;
    float invsy = (yy == 0 || yy == HH - 1) ? (1.f / 1.75f) : 0.5f;
    float invsx = (xx == 0 || xx == WW - 1) ? (1.f / 1.75f) : 0.5f;
    float wyv[4], wxv[4];
    #pragma unroll
    for (int t = 0; t < 4; t++) {
        wyv[t] = ((unsigned)(gy0 + 2 * ly + t) < H2) ? dbase(t) * invsy : 0.f;
        wxv[t] = ((unsigned)(gx0 + 2 * lx + t) < W2) ? dbase(t) * invsx : 0.f;
    }
    int sbase = (2 * ly) * TWW + 2 * lx;
    int opix = yy * WW + xx;

    for (int g = 0; g < NG; g++) {
        const float4* p = src + (size_t)g * HW;
        #pragma unroll
        for (int k = 0; k < NPOS; k++) {
            int i = tid + 256 * k;
            if (i < TWNW) {
                const float4* q = p + rbase[k];
                float wx0 = rwx[k][0], wx1 = rwx[k][1], wx2 = rwx[k][2];
                float4 acc = make_float4(0.f, 0.f, 0.f, 0.f);
                #pragma unroll
                for (int j = 0; j < 3; j++) {
                    float4 v0 = q[j * WW], v1 = q[j * WW + 1], v2 = q[j * WW + 2];
                    float wy = rwy[k][j];
                    acc.x += wy * (wx0 * v0.x + wx1 * v1.x + wx2 * v2.x);
                    acc.y += wy * (wx0 * v0.y + wx1 * v1.y + wx2 * v2.y);
                    acc.z += wy * (wx0 * v0.z + wx1 * v1.z + wx2 * v2.z);
                    acc.w += wy * (wx0 * v0.w + wx1 * v1.w + wx2 * v2.w);
                }
                s_w[i] = acc;
            }
        }
        __syncthreads();
        float4 acc = make_float4(0.f, 0.f, 0.f, 0.f);
        #pragma unroll
        for (int ty = 0; ty < 4; ty++) {
            const float4* sr = s_w + sbase + ty * TWW;
            float4 rowv = make_float4(0.f, 0.f, 0.f, 0.f);
            #pragma unroll
            for (int tx = 0; tx < 4; tx++) {
                float4 v = sr[tx];
                float w = wxv[tx];
                rowv.x += w * v.x; rowv.y += w * v.y;
                rowv.z += w * v.z; rowv.w += w * v.w;
            }
            float w = wyv[ty];
            acc.x += w * rowv.x; acc.y += w * rowv.y;
            acc.z += w * rowv.z; acc.w += w * rowv.w;
        }
        dstb[(size_t)(4 * g + 0) * HW + opix] = acc.x;
        dstb[(size_t)(4 * g + 1) * HW + opix] = acc.y;
        dstb[(size_t)(4 * g + 2) * HW + opix] = acc.z;
        dstb[(size_t)(4 * g + 3) * HW + opix] = acc.w;
        __syncthreads();
    }
}

// -------- 3x3 conv 50->2: smem-tiled 32x32, 2-channel double-buffer -----------
__global__ void __launch_bounds__(256) k_conv(
        const float* __restrict__ x, const float* __restrict__ res,
        const float* __restrict__ Wc, const float* __restrict__ bias,
        float* __restrict__ out) {
    __shared__ float sw[2 * CINc * 9];
    __shared__ float tile[2][2][CTW * CTP];
    int tid = threadIdx.x;
    for (int i = tid; i < 2 * CINc * 9; i += 256) sw[i] = Wc[i];

    int b = blockIdx.z;
    int x0 = blockIdx.x * CTS, y0 = blockIdx.y * CTS;
    int lx = tid & 31, ly4 = tid >> 5;

    const float* xb = x + (size_t)b * 2 * NF * HW;
    const float* wb = g_warped + (size_t)b * NF * HW;
    const float* rb = res + (size_t)b * 2 * HW;

    int  sofs[CNL], gofs[CNL];
    bool inb[CNL];
    #pragma unroll
    for (int k = 0; k < CNL; k++) {
        int i = tid + 256 * k;
        bool valid = (i < CTW * CTW);
        int r = i / CTW, col = i - r * CTW;
        int gy = y0 - 1 + r, gx = x0 - 1 + col;
        inb[k]  = valid && ((unsigned)gy < HH) && ((unsigned)gx < WW);
        sofs[k] = valid ? (r * CTP + col) : 0;
        gofs[k] = inb[k] ? (gy * WW + gx) : 0;
        if (!valid) sofs[k] = -1;
    }

    float a0[4] = {0.f, 0.f, 0.f, 0.f};
    float a1[4] = {0.f, 0.f, 0.f, 0.f};

    // prologue: stage channels 0,1 into stage 0
    float ld0[CNL], ld1[CNL];
    #pragma unroll
    for (int k = 0; k < CNL; k++) {
        ld0[k] = inb[k] ? xb[gofs[k]] : 0.f;
        ld1[k] = inb[k] ? xb[HW + gofs[k]] : 0.f;
    }
    #pragma unroll
    for (int k = 0; k < CNL; k++)
        if (sofs[k] >= 0) { tile[0][0][sofs[k]] = ld0[k]; tile[0][1][sofs[k]] = ld1[k]; }
    __syncthreads();

    int base = (ly4 * 4) * CTP + lx;

    #pragma unroll 1
    for (int cp = 0; cp < CINc / 2; cp++) {
        int c0 = 2 * cp;
        // prefetch channels c0+2, c0+3 into registers (overlaps compute)
        if (cp + 1 < CINc / 2) {
            int ca = c0 + 2, cb2 = c0 + 3;
            const float* pA = (ca < 32) ? (xb + (size_t)ca * HW)
                            : (ca < 48) ? (wb + (size_t)(ca - 32) * HW)
                                        : (rb + (size_t)(ca - 48) * HW);
            const float* pB = (cb2 < 32) ? (xb + (size_t)cb2 * HW)
                            : (cb2 < 48) ? (wb + (size_t)(cb2 - 32) * HW)
                                         : (rb + (size_t)(cb2 - 48) * HW);
            #pragma unroll
            for (int k = 0; k < CNL; k++) {
                ld0[k] = inb[k] ? pA[gofs[k]] : 0.f;
                ld1[k] = inb[k] ? pB[gofs[k]] : 0.f;
            }
        }

        // compute the two live channels
        #pragma unroll
        for (int h = 0; h < 2; h++) {
            int c = c0 + h;
            const float* tl = tile[cp & 1][h];
            const float* q = sw + c * 9;
            const float* u = sw + CINc * 9 + c * 9;
            float q0 = q[0], q1 = q[1], q2 = q[2], q3 = q[3], q4 = q[4];
            float q5 = q[5], q6 = q[6], q7 = q[7], q8 = q[8];
            float u0 = u[0], u1 = u[1], u2 = u[2], u3 = u[3], u4 = u[4];
            float u5 = u[5], u6 = u[6], u7 = u[7], u8 = u[8];
            float v[6][3];
            #pragma unroll
            for (int r6 = 0; r6 < 6; r6++) {
                v[r6][0] = tl[base + r6 * CTP];
                v[r6][1] = tl[base + r6 * CTP + 1];
                v[r6][2] = tl[base + r6 * CTP + 2];
            }
            #pragma unroll
            for (int k = 0; k < 4; k++) {
                a0[k] += v[k][0] * q0 + v[k][1] * q1 + v[k][2] * q2
                       + v[k+1][0] * q3 + v[k+1][1] * q4 + v[k+1][2] * q5
                       + v[k+2][0] * q6 + v[k+2][1] * q7 + v[k+2][2] * q8;
                a1[k] += v[k][0] * u0 + v[k][1] * u1 + v[k][2] * u2
                       + v[k+1][0] * u3 + v[k+1][1] * u4 + v[k+1][2] * u5
                       + v[k+2][0] * u6 + v[k+2][1] * u7 + v[k+2][2] * u8;
            }
        }

        // store prefetched pair into the other stage, one sync per pair
        if (cp + 1 < CINc / 2) {
            float* tA = tile[(cp + 1) & 1][0];
            float* tB = tile[(cp + 1) & 1][1];
            #pragma unroll
            for (int k = 0; k < CNL; k++)
                if (sofs[k] >= 0) { tA[sofs[k]] = ld0[k]; tB[sofs[k]] = ld1[k]; }
        }
        __syncthreads();
    }

    float b0 = bias[0], b1 = bias[1];
    float* o = g_adj + (size_t)b * 2 * HW;
    float* ob = out + (size_t)b * 2 * NF * HW;
    #pragma unroll
    for (int k = 0; k < 4; k++) {
        int pc = (y0 + ly4 * 4 + k) * WW + x0 + lx;
        o[pc]      = a0[k] + b0;
        o[HW + pc] = a1[k] + b1;
        // pass-through: out[b][0..15] = x[b][0..15] (free under pipeline latency)
        #pragma unroll
        for (int c = 0; c < NF; c++)
            ob[(size_t)c * HW + pc] = xb[(size_t)c * HW + pc];
    }
}

// -------- fused: warp a1024 by b1024 (tables) -> downsample*0.5 + adj ----------
__global__ void __launch_bounds__(256) k_combine() {
    __shared__ float2 s_w[TWNW];
    int b = blockIdx.z;
    int x0 = blockIdx.x * TSW, y0 = blockIdx.y * TSW;
    int gx0 = 2 * x0 - 1, gy0 = 2 * y0 - 1;
    int tid = threadIdx.x;

    const float2* bf = g_b1024 + (size_t)b * HW2;
    const float2* af = g_a1024 + (size_t)b * HW2;

    #pragma unroll
    for (int k = 0; k < NPOS; k++) {
        int i = tid + 256 * k;
        if (i < TWNW) {
            int r = i / TWW, cc = i - r * TWW;
            int Y = min(max(gy0 + r, 0), H2 - 1);
            int X = min(max(gx0 + cc, 0), W2 - 1);
            float2 f = bf[Y * W2 + X];
            float sx = (float)(gx0 + cc) + f.x;
            float sy = (float)(gy0 + r) + f.y;
            float xf = floorf(sx), yf = floorf(sy);
            float fx = sx - xf, fy = sy - yf;
            int ix0 = (int)xf, iy0 = (int)yf;
            bool bx0 = (unsigned)ix0 < W2, bx1 = (unsigned)(ix0 + 1) < W2;
            bool by0 = (unsigned)iy0 < H2, by1 = (unsigned)(iy0 + 1) < H2;
            float wx0 = bx0 ? (1.f - fx) : 0.f, wx1 = bx1 ? fx : 0.f;
            float wy0 = by0 ? (1.f - fy) : 0.f, wy1 = by1 ? fy : 0.f;
            float w00 = wy0 * wx0, w01 = wy0 * wx1, w10 = wy1 * wx0, w11 = wy1 * wx1;
            int cx0 = min(max(ix0, 0), W2 - 1), cx1 = min(max(ix0 + 1, 0), W2 - 1);
            int cy0 = min(max(iy0, 0), H2 - 1), cy1 = min(max(iy0 + 1, 0), H2 - 1);
            int o00 = cy0 * W2 + cx0;
            int dxo = cx1 - cx0;
            int o10 = o00 + (cy1 - cy0) * W2;
            float2 v00 = af[o00], v01 = af[o00 + dxo];
            float2 v10 = af[o10], v11 = af[o10 + dxo];
            s_w[i] = make_float2(
                w00 * v00.x + w01 * v01.x + w10 * v10.x + w11 * v11.x,
                w00 * v00.y + w01 * v01.y + w10 * v10.y + w11 * v11.y);
        }
    }
    __syncthreads();

    int lx = tid & (TSW - 1), ly = tid >> 4;
    int yy = y0 + ly, xx = x0 + lx;
    float invsy = (yy == 0 || yy == HH - 1) ? (1.f / 1.75f) : 0.5f;
    float invsx = (xx == 0 || xx == WW - 1) ? (1.f / 1.75f) : 0.5f;
    float wyv[4], wxv[4];
    #pragma unroll
    for (int t = 0; t < 4; t++) {
        wyv[t] = ((unsigned)(gy0 + 2 * ly + t) < H2) ? dbase(t) * invsy : 0.f;
        wxv[t] = ((unsigned)(gx0 + 2 * lx + t) < W2) ? dbase(t) * invsx : 0.f;
    }
    int sbase = (2 * ly) * TWW + 2 * lx;
    float accx = 0.f, accy = 0.f;
    #pragma unroll
    for (int ty = 0; ty < 4; ty++) {
        const float2* sr = s_w + sbase + ty * TWW;
        float rx = wxv[0] * sr[0].x + wxv[1] * sr[1].x + wxv[2] * sr[2].x + wxv[3] * sr[3].x;
        float ry = wxv[0] * sr[0].y + wxv[1] * sr[1].y + wxv[2] * sr[2].y + wxv[3] * sr[3].y;
        accx += wyv[ty] * rx;
        accy += wyv[ty] * ry;
    }
    int p = yy * WW + xx;
    const float* ad = g_adj + (size_t)b * 2 * HW;
    float* nr = g_newres + (size_t)b * 2 * HW;
    nr[p]      = ad[p]      + 0.5f * accx;
    nr[HW + p] = ad[HW + p] + 0.5f * accy;
}

// -------- launch --------
extern "C" void kernel_launch(void* const* d_in, const int* in_sizes, int n_in,
                              void* d_out, int out_size) {
    const float* x    = (const float*)d_in[0];
    const float* res  = (const float*)d_in[1];
    const float* Wc   = (const float*)d_in[2];
    const float* bias = (const float*)d_in[3];
    float* out = (float*)d_out;

    const int T = 256;
    dim3 gp((BB * HW + T - 1) / T);
    dim3 gu((BB * H2 * (W2 / 4) + T - 1) / T);
    dim3 gcv(WW / CTS, HH / CTS, BB);
    dim3 gw(HH / TSW, WW / TSW, BB);

    k_pack<<<gp, T>>>(x);                         // tgt -> g_tgt4 (512, packed)
    k_up_res<<<gu, T>>>(res, 0, 0);               // res -> g_a1024 (*2)
    k_warpdown<<<gw, T>>>(nullptr, 0, 0);         // 9-tap warp by a1024 -> g_warped
    k_conv<<<gcv, T>>>(x, res, Wc, bias, out);    // adj + src pass-through
    k_up_res<<<gu, T>>>(nullptr, 1, 1);           // adj -> g_b1024 (*2)
    k_combine<<<gw, T>>>();                       // -> g_newres
    k_up_res<<<gu, T>>>(nullptr, 2, 2);           // new_res -> g_nr1024 (*2)
    k_warpdown<<<gw, T>>>(out, 1, 1);             // 9-tap warp by nr1024 -> out[16..31]
}

// round 17
// speedup vs baseline: 1.0792x; 1.0266x over previous
#include <cuda_runtime.h>

#define BB 2
#define NF 16
#define NG 4               // channel groups of 4 (float4)
#define HH 512
#define WW 512
#define H2 1024
#define W2 1024
#define CINc 50
#define HW (HH*WW)
#define HW2 (H2*W2)

// warp/combine tiles: 16x16 outputs at 512-res
#define TSW 16
#define TWW 34             // 2*TSW+2
#define TWNW (TWW*TWW)     // 1156
#define NPOS 5             // ceil(TWNW/256)

// conv tile (R11 geometry — proven best)
#define CTS 32
#define CTW 34
#define CTP 36
#define CNL 5

// -------- scratch (device globals; referenced ONLY from device code) --------
__device__ float4 g_tgt4 [(size_t)BB*NG*HW];   // tgt @512, channel-packed x4 (L2-resident)
__device__ float  g_warped[(size_t)BB*NF*HW];  // warped tgt @512, planar
__device__ float  g_adj  [(size_t)BB*2*HW];    // conv output, planar
__device__ float  g_newres[(size_t)BB*2*HW];   // combined residual, planar
__device__ float2 g_a1024[(size_t)BB*HW2];     // up(res)*2, interleaved
__device__ float2 g_b1024[(size_t)BB*HW2];     // up(adj)*2
__device__ float2 g_nr1024[(size_t)BB*HW2];    // up(new_res)*2

// -------- resize helpers (jax.image.resize bilinear; validated R1) --------
__device__ __forceinline__ void up_taps(int i, int n_in, int& t0, int& t1,
                                        float& w0, float& w1) {
    int k = i >> 1;
    if ((i & 1) == 0) { t0 = k - 1; t1 = k;     w0 = 0.25f; w1 = 0.75f; }
    else              { t0 = k;     t1 = k + 1; w0 = 0.75f; w1 = 0.25f; }
    if (t0 < 0)     { t0 = t1; w0 = 0.f; w1 = 1.f; }
    if (t1 >= n_in) { t1 = t0; w1 = 0.f; w0 = 1.f; }
}
__device__ __forceinline__ float dbase(int t) { return (t == 0 || t == 3) ? 0.25f : 0.75f; }

// composite 1D weights: warp-bilinear over the upsampled axis collapsed onto
// 3 source taps (validated R14).
__device__ __forceinline__ void compose_dim(int i0, float fr, int& base, float w[3]) {
    bool m0 = (unsigned)i0 < (unsigned)H2;
    bool m1 = (unsigned)(i0 + 1) < (unsigned)H2;
    int c0 = min(max(i0, 0), H2 - 1);
    int c1 = min(max(i0 + 1, 0), H2 - 1);
    int t0a, t1a, t0b, t1b; float a0, a1, b0, b1;
    up_taps(c0, HH, t0a, t1a, a0, a1);
    up_taps(c1, HH, t0b, t1b, b0, b1);
    float f0 = m0 ? (1.f - fr) : 0.f;
    float f1 = m1 ? fr : 0.f;
    int bs = min(min(t0a, t1a), min(t0b, t1b));
    if (bs > HH - 3) bs = HH - 3;
    #pragma unroll
    for (int j = 0; j < 3; j++) {
        float wv = 0.f;
        wv += (t0a - bs == j) ? f0 * a0 : 0.f;
        wv += (t1a - bs == j) ? f0 * a1 : 0.f;
        wv += (t0b - bs == j) ? f1 * b0 : 0.f;
        wv += (t1b - bs == j) ? f1 * b1 : 0.f;
        w[j] = wv;
    }
    base = bs;
}

// -------- kernel 1: pack tgt channels into float4 groups @512 (R14 form) ------
__global__ void __launch_bounds__(256) k_pack(const float* __restrict__ x) {
    int idx = blockIdx.x * blockDim.x + threadIdx.x;
    if (idx >= BB * HW) return;
    int pix = idx & (HW - 1), b = idx >> 18;
    const float* xb = x + ((size_t)b * 2 * NF + NF) * HW + pix;
    float4* ob = g_tgt4 + (size_t)b * NG * HW + pix;
    #pragma unroll
    for (int g = 0; g < NG; g++) {
        float4 o;
        o.x = xb[(size_t)(4 * g + 0) * HW];
        o.y = xb[(size_t)(4 * g + 1) * HW];
        o.z = xb[(size_t)(4 * g + 2) * HW];
        o.w = xb[(size_t)(4 * g + 3) * HW];
        ob[(size_t)g * HW] = o;
    }
}

// -------- kernel 2: upsample a 2ch 512 field ->1024, *2, interleaved float2 ----
__global__ void __launch_bounds__(256) k_up_res(const float* __restrict__ ext,
                                                int src_sel, int dst_sel) {
    int idx = blockIdx.x * blockDim.x + threadIdx.x;
    if (idx >= BB * H2 * (W2 / 4)) return;
    int xq = idx & (W2 / 4 - 1);
    int yy = (idx >> 8) & (H2 - 1);
    int b  = idx >> 18;
    int m = 2 * xq;
    int mm1 = max(m - 1, 0), mp2 = min(m + 2, WW - 1);
    float a00 = (m == 0) ? 0.f : 0.25f,  a01 = (m == 0) ? 1.f : 0.75f;
    float a30 = (m == WW - 2) ? 1.f : 0.75f, a31 = (m == WW - 2) ? 0.f : 0.25f;
    int ty0, ty1; float wy0, wy1;
    up_taps(yy, HH, ty0, ty1, wy0, wy1);
    int r0 = ty0 * WW, r1 = ty1 * WW;

    const float* src = (src_sel == 0) ? ext : ((src_sel == 1) ? g_adj : g_newres);
    const float* p0 = src + (size_t)b * 2 * HW;
    const float* p1 = p0 + HW;
    float ox[4], oy[4];
    {
        float s0 = p0[r0 + mm1]   * wy0 + p0[r1 + mm1]   * wy1;
        float s1 = p0[r0 + m]     * wy0 + p0[r1 + m]     * wy1;
        float s2 = p0[r0 + m + 1] * wy0 + p0[r1 + m + 1] * wy1;
        float s3 = p0[r0 + mp2]   * wy0 + p0[r1 + mp2]   * wy1;
        ox[0] = a00 * s0 + a01 * s1;  ox[1] = 0.75f * s1 + 0.25f * s2;
        ox[2] = 0.25f * s1 + 0.75f * s2;  ox[3] = a30 * s2 + a31 * s3;
    }
    {
        float s0 = p1[r0 + mm1]   * wy0 + p1[r1 + mm1]   * wy1;
        float s1 = p1[r0 + m]     * wy0 + p1[r1 + m]     * wy1;
        float s2 = p1[r0 + m + 1] * wy0 + p1[r1 + m + 1] * wy1;
        float s3 = p1[r0 + mp2]   * wy0 + p1[r1 + mp2]   * wy1;
        oy[0] = a00 * s0 + a01 * s1;  oy[1] = 0.75f * s1 + 0.25f * s2;
        oy[2] = 0.25f * s1 + 0.75f * s2;  oy[3] = a30 * s2 + a31 * s3;
    }
    float2* dst = (dst_sel == 0) ? g_a1024 : ((dst_sel == 1) ? g_b1024 : g_nr1024);
    float4* ob = (float4*)(dst + (size_t)b * HW2 + (size_t)yy * W2 + 4 * xq);
    ob[0] = make_float4(2.f * ox[0], 2.f * oy[0], 2.f * ox[1], 2.f * oy[1]);
    ob[1] = make_float4(2.f * ox[2], 2.f * oy[2], 2.f * ox[3], 2.f * oy[3]);
}

// -------- fused: composite 9-tap gather -> warp+downsample, PIPELINED ---------
__global__ void __launch_bounds__(256) k_warpdown(
        float* __restrict__ out, int field_sel, int to_final) {
    __shared__ float4 s_w[2][TWNW];      // double-buffered warped planes
    int b = blockIdx.z;
    int x0 = blockIdx.x * TSW, y0 = blockIdx.y * TSW;
    int gx0 = 2 * x0 - 1, gy0 = 2 * y0 - 1;
    int tid = threadIdx.x;

    const float2* fld = ((field_sel == 0) ? g_a1024 : g_nr1024) + (size_t)b * HW2;

    int   rbase[NPOS];
    float rwx[NPOS][3], rwy[NPOS][3];
    #pragma unroll
    for (int k = 0; k < NPOS; k++) {
        int i = tid + 256 * k;
        if (i < TWNW) {
            int r = i / TWW, cc = i - r * TWW;
            int Y = min(max(gy0 + r, 0), H2 - 1);
            int X = min(max(gx0 + cc, 0), W2 - 1);
            float2 f = fld[Y * W2 + X];
            float sx = (float)(gx0 + cc) + f.x;
            float sy = (float)(gy0 + r) + f.y;
            float xf = floorf(sx), yf = floorf(sy);
            float fx = sx - xf, fy = sy - yf;
            int ix0 = (int)xf, iy0 = (int)yf;
            int bxv, byv;
            compose_dim(ix0, fx, bxv, rwx[k]);
            compose_dim(iy0, fy, byv, rwy[k]);
            rbase[k] = byv * WW + bxv;
        }
    }

    const float4* src = g_tgt4 + (size_t)b * NG * HW;
    float* dstb = to_final ? (out + ((size_t)b * 2 * NF + NF) * HW)
                           : (g_warped + (size_t)b * NF * HW);
    int lx = tid & (TSW - 1), ly = tid >> 4;
    int yy = y0 + ly, xx = x0 + lx;
    float invsy = (yy == 0 || yy == HH - 1) ? (1.f / 1.75f) : 0.5f;
    float invsx = (xx == 0 || xx == WW - 1) ? (1.f / 1.75f) : 0.5f;
    float wyv[4], wxv[4];
    #pragma unroll
    for (int t = 0; t < 4; t++) {
        wyv[t] = ((unsigned)(gy0 + 2 * ly + t) < H2) ? dbase(t) * invsy : 0.f;
        wxv[t] = ((unsigned)(gx0 + 2 * lx + t) < W2) ? dbase(t) * invsx : 0.f;
    }
    int sbase = (2 * ly) * TWW + 2 * lx;
    int opix = yy * WW + xx;

    // gather lambda: group g -> buffer buf
    auto gather = [&](int g, float4* buf) {
        const float4* p = src + (size_t)g * HW;
        #pragma unroll
        for (int k = 0; k < NPOS; k++) {
            int i = tid + 256 * k;
            if (i < TWNW) {
                const float4* q = p + rbase[k];
                float wx0 = rwx[k][0], wx1 = rwx[k][1], wx2 = rwx[k][2];
                float4 acc = make_float4(0.f, 0.f, 0.f, 0.f);
                #pragma unroll
                for (int j = 0; j < 3; j++) {
                    float4 v0 = q[j * WW], v1 = q[j * WW + 1], v2 = q[j * WW + 2];
                    float wy = rwy[k][j];
                    acc.x += wy * (wx0 * v0.x + wx1 * v1.x + wx2 * v2.x);
                    acc.y += wy * (wx0 * v0.y + wx1 * v1.y + wx2 * v2.y);
                    acc.z += wy * (wx0 * v0.z + wx1 * v1.z + wx2 * v2.z);
                    acc.w += wy * (wx0 * v0.w + wx1 * v1.w + wx2 * v2.w);
                }
                buf[i] = acc;
            }
        }
    };

    gather(0, s_w[0]);
    __syncthreads();

    for (int g = 0; g < NG; g++) {
        // prefetch next group into the other buffer (overlaps downsample below)
        if (g + 1 < NG) gather(g + 1, s_w[(g + 1) & 1]);

        const float4* sb = s_w[g & 1];
        float4 acc = make_float4(0.f, 0.f, 0.f, 0.f);
        #pragma unroll
        for (int ty = 0; ty < 4; ty++) {
            const float4* sr = sb + sbase + ty * TWW;
            float4 rowv = make_float4(0.f, 0.f, 0.f, 0.f);
            #pragma unroll
            for (int tx = 0; tx < 4; tx++) {
                float4 v = sr[tx];
                float w = wxv[tx];
                rowv.x += w * v.x; rowv.y += w * v.y;
                rowv.z += w * v.z; rowv.w += w * v.w;
            }
            float w = wyv[ty];
            acc.x += w * rowv.x; acc.y += w * rowv.y;
            acc.z += w * rowv.z; acc.w += w * rowv.w;
        }
        dstb[(size_t)(4 * g + 0) * HW + opix] = acc.x;
        dstb[(size_t)(4 * g + 1) * HW + opix] = acc.y;
        dstb[(size_t)(4 * g + 2) * HW + opix] = acc.z;
        dstb[(size_t)(4 * g + 3) * HW + opix] = acc.w;
        __syncthreads();
    }
}

// -------- 3x3 conv 50->2: smem-tiled 32x32, 2-channel double-buffer (R16) -----
__global__ void __launch_bounds__(256) k_conv(
        const float* __restrict__ x, const float* __restrict__ res,
        const float* __restrict__ Wc, const float* __restrict__ bias,
        float* __restrict__ out) {
    __shared__ float sw[2 * CINc * 9];
    __shared__ float tile[2][2][CTW * CTP];
    int tid = threadIdx.x;
    for (int i = tid; i < 2 * CINc * 9; i += 256) sw[i] = Wc[i];

    int b = blockIdx.z;
    int x0 = blockIdx.x * CTS, y0 = blockIdx.y * CTS;
    int lx = tid & 31, ly4 = tid >> 5;

    const float* xb = x + (size_t)b * 2 * NF * HW;
    const float* wb = g_warped + (size_t)b * NF * HW;
    const float* rb = res + (size_t)b * 2 * HW;

    int  sofs[CNL], gofs[CNL];
    bool inb[CNL];
    #pragma unroll
    for (int k = 0; k < CNL; k++) {
        int i = tid + 256 * k;
        bool valid = (i < CTW * CTW);
        int r = i / CTW, col = i - r * CTW;
        int gy = y0 - 1 + r, gx = x0 - 1 + col;
        inb[k]  = valid && ((unsigned)gy < HH) && ((unsigned)gx < WW);
        sofs[k] = valid ? (r * CTP + col) : 0;
        gofs[k] = inb[k] ? (gy * WW + gx) : 0;
        if (!valid) sofs[k] = -1;
    }

    float a0[4] = {0.f, 0.f, 0.f, 0.f};
    float a1[4] = {0.f, 0.f, 0.f, 0.f};

    float ld0[CNL], ld1[CNL];
    #pragma unroll
    for (int k = 0; k < CNL; k++) {
        ld0[k] = inb[k] ? xb[gofs[k]] : 0.f;
        ld1[k] = inb[k] ? xb[HW + gofs[k]] : 0.f;
    }
    #pragma unroll
    for (int k = 0; k < CNL; k++)
        if (sofs[k] >= 0) { tile[0][0][sofs[k]] = ld0[k]; tile[0][1][sofs[k]] = ld1[k]; }
    __syncthreads();

    int base = (ly4 * 4) * CTP + lx;

    #pragma unroll 1
    for (int cp = 0; cp < CINc / 2; cp++) {
        int c0 = 2 * cp;
        if (cp + 1 < CINc / 2) {
            int ca = c0 + 2, cb2 = c0 + 3;
            const float* pA = (ca < 32) ? (xb + (size_t)ca * HW)
                            : (ca < 48) ? (wb + (size_t)(ca - 32) * HW)
                                        : (rb + (size_t)(ca - 48) * HW);
            const float* pB = (cb2 < 32) ? (xb + (size_t)cb2 * HW)
                            : (cb2 < 48) ? (wb + (size_t)(cb2 - 32) * HW)
                                         : (rb + (size_t)(cb2 - 48) * HW);
            #pragma unroll
            for (int k = 0; k < CNL; k++) {
                ld0[k] = inb[k] ? pA[gofs[k]] : 0.f;
                ld1[k] = inb[k] ? pB[gofs[k]] : 0.f;
            }
        }

        #pragma unroll
        for (int h = 0; h < 2; h++) {
            int c = c0 + h;
            const float* tl = tile[cp & 1][h];
            const float* q = sw + c * 9;
            const float* u = sw + CINc * 9 + c * 9;
            float q0 = q[0], q1 = q[1], q2 = q[2], q3 = q[3], q4 = q[4];
            float q5 = q[5], q6 = q[6], q7 = q[7], q8 = q[8];
            float u0 = u[0], u1 = u[1], u2 = u[2], u3 = u[3], u4 = u[4];
            float u5 = u[5], u6 = u[6], u7 = u[7], u8 = u[8];
            float v[6][3];
            #pragma unroll
            for (int r6 = 0; r6 < 6; r6++) {
                v[r6][0] = tl[base + r6 * CTP];
                v[r6][1] = tl[base + r6 * CTP + 1];
                v[r6][2] = tl[base + r6 * CTP + 2];
            }
            #pragma unroll
            for (int k = 0; k < 4; k++) {
                a0[k] += v[k][0] * q0 + v[k][1] * q1 + v[k][2] * q2
                       + v[k+1][0] * q3 + v[k+1][1] * q4 + v[k+1][2] * q5
                       + v[k+2][0] * q6 + v[k+2][1] * q7 + v[k+2][2] * q8;
                a1[k] += v[k][0] * u0 + v[k][1] * u1 + v[k][2] * u2
                       + v[k+1][0] * u3 + v[k+1][1] * u4 + v[k+1][2] * u5
                       + v[k+2][0] * u6 + v[k+2][1] * u7 + v[k+2][2] * u8;
            }
        }

        if (cp + 1 < CINc / 2) {
            float* tA = tile[(cp + 1) & 1][0];
            float* tB = tile[(cp + 1) & 1][1];
            #pragma unroll
            for (int k = 0; k < CNL; k++)
                if (sofs[k] >= 0) { tA[sofs[k]] = ld0[k]; tB[sofs[k]] = ld1[k]; }
        }
        __syncthreads();
    }

    float b0 = bias[0], b1 = bias[1];
    float* o = g_adj + (size_t)b * 2 * HW;
    float* ob = out + (size_t)b * 2 * NF * HW;
    #pragma unroll
    for (int k = 0; k < 4; k++) {
        int pc = (y0 + ly4 * 4 + k) * WW + x0 + lx;
        o[pc]      = a0[k] + b0;
        o[HW + pc] = a1[k] + b1;
        #pragma unroll
        for (int c = 0; c < NF; c++)
            ob[(size_t)c * HW + pc] = xb[(size_t)c * HW + pc];
    }
}

// -------- fused: warp a1024 by b1024 (tables) -> downsample*0.5 + adj ----------
__global__ void __launch_bounds__(256) k_combine() {
    __shared__ float2 s_w[TWNW];
    int b = blockIdx.z;
    int x0 = blockIdx.x * TSW, y0 = blockIdx.y * TSW;
    int gx0 = 2 * x0 - 1, gy0 = 2 * y0 - 1;
    int tid = threadIdx.x;

    const float2* bf = g_b1024 + (size_t)b * HW2;
    const float2* af = g_a1024 + (size_t)b * HW2;

    #pragma unroll
    for (int k = 0; k < NPOS; k++) {
        int i = tid + 256 * k;
        if (i < TWNW) {
            int r = i / TWW, cc = i - r * TWW;
            int Y = min(max(gy0 + r, 0), H2 - 1);
            int X = min(max(gx0 + cc, 0), W2 - 1);
            float2 f = bf[Y * W2 + X];
            float sx = (float)(gx0 + cc) + f.x;
            float sy = (float)(gy0 + r) + f.y;
            float xf = floorf(sx), yf = floorf(sy);
            float fx = sx - xf, fy = sy - yf;
            int ix0 = (int)xf, iy0 = (int)yf;
            bool bx0 = (unsigned)ix0 < W2, bx1 = (unsigned)(ix0 + 1) < W2;
            bool by0 = (unsigned)iy0 < H2, by1 = (unsigned)(iy0 + 1) < H2;
            float wx0 = bx0 ? (1.f - fx) : 0.f, wx1 = bx1 ? fx : 0.f;
            float wy0 = by0 ? (1.f - fy) : 0.f, wy1 = by1 ? fy : 0.f;
            float w00 = wy0 * wx0, w01 = wy0 * wx1, w10 = wy1 * wx0, w11 = wy1 * wx1;
            int cx0 = min(max(ix0, 0), W2 - 1), cx1 = min(max(ix0 + 1, 0), W2 - 1);
            int cy0 = min(max(iy0, 0), H2 - 1), cy1 = min(max(iy0 + 1, 0), H2 - 1);
            int o00 = cy0 * W2 + cx0;
            int dxo = cx1 - cx0;
            int o10 = o00 + (cy1 - cy0) * W2;
            float2 v00 = af[o00], v01 = af[o00 + dxo];
            float2 v10 = af[o10], v11 = af[o10 + dxo];
            s_w[i] = make_float2(
                w00 * v00.x + w01 * v01.x + w10 * v10.x + w11 * v11.x,
                w00 * v00.y + w01 * v01.y + w10 * v10.y + w11 * v11.y);
        }
    }
    __syncthreads();

    int lx = tid & (TSW - 1), ly = tid >> 4;
    int yy = y0 + ly, xx = x0 + lx;
    float invsy = (yy == 0 || yy == HH - 1) ? (1.f / 1.75f) : 0.5f;
    float invsx = (xx == 0 || xx == WW - 1) ? (1.f / 1.75f) : 0.5f;
    float wyv[4], wxv[4];
    #pragma unroll
    for (int t = 0; t < 4; t++) {
        wyv[t] = ((unsigned)(gy0 + 2 * ly + t) < H2) ? dbase(t) * invsy : 0.f;
        wxv[t] = ((unsigned)(gx0 + 2 * lx + t) < W2) ? dbase(t) * invsx : 0.f;
    }
    int sbase = (2 * ly) * TWW + 2 * lx;
    float accx = 0.f, accy = 0.f;
    #pragma unroll
    for (int ty = 0; ty < 4; ty++) {
        const float2* sr = s_w + sbase + ty * TWW;
        float rx = wxv[0] * sr[0].x + wxv[1] * sr[1].x + wxv[2] * sr[2].x + wxv[3] * sr[3].x;
        float ry = wxv[0] * sr[0].y + wxv[1] * sr[1].y + wxv[2] * sr[2].y + wxv[3] * sr[3].y;
        accx += wyv[ty] * rx;
        accy += wyv[ty] * ry;
    }
    int p = yy * WW + xx;
    const float* ad = g_adj + (size_t)b * 2 * HW;
    float* nr = g_newres + (size_t)b * 2 * HW;
    nr[p]      = ad[p]      + 0.5f * accx;
    nr[HW + p] = ad[HW + p] + 0.5f * accy;
}

// -------- launch --------
extern "C" void kernel_launch(void* const* d_in, const int* in_sizes, int n_in,
                              void* d_out, int out_size) {
    const float* x    = (const float*)d_in[0];
    const float* res  = (const float*)d_in[1];
    const float* Wc   = (const float*)d_in[2];
    const float* bias = (const float*)d_in[3];
    float* out = (float*)d_out;

    const int T = 256;
    dim3 gp((BB * HW + T - 1) / T);
    dim3 gu((BB * H2 * (W2 / 4) + T - 1) / T);
    dim3 gcv(WW / CTS, HH / CTS, BB);
    dim3 gw(HH / TSW, WW / TSW, BB);

    k_pack<<<gp, T>>>(x);                         // tgt -> g_tgt4 (512, packed)
    k_up_res<<<gu, T>>>(res, 0, 0);               // res -> g_a1024 (*2)
    k_warpdown<<<gw, T>>>(nullptr, 0, 0);         // 9-tap warp by a1024 -> g_warped
    k_conv<<<gcv, T>>>(x, res, Wc, bias, out);    // adj + src pass-through
    k_up_res<<<gu, T>>>(nullptr, 1, 1);           // adj -> g_b1024 (*2)
    k_combine<<<gw, T>>>();                       // -> g_newres
    k_up_res<<<gu, T>>>(nullptr, 2, 2);           // new_res -> g_nr1024 (*2)
    k_warpdown<<<gw, T>>>(out, 1, 1);             // 9-tap warp by nr1024 -> out[16..31]
}